// round 13
// baseline (speedup 1.0000x reference)
#include <cuda_runtime.h>
#include <cuda_fp16.h>
#include <cuda_bf16.h>

#define BB 8
#define TT 12
#define NN 1500
#define BNS 12000
#define OUTD 3

// ---- scratch (device globals, no runtime alloc) ----
static __device__ __half g_h0h[(size_t)TT * BNS * 64];   // layer0 hidden fp16 [t*BNS+s][u]
static __device__ float  g_xp [(size_t)TT * BNS * 256];  // layer1 input proj (q-permuted)
static __device__ float  g_h  [BNS * 64];
static __device__ __half g_hph[BNS * 64];
static __device__ float  g_es [BNS * 4];
static __device__ float  g_ed [BNS * 4];
static __device__ float  g_gmax[BB * 4];
static __device__ float  g_ho [BNS * 64];
static __device__ float  g_h2 [BNS * 64];

__device__ __forceinline__ float sigf(float x)   { return 1.0f / (1.0f + __expf(-x)); }
__device__ __forceinline__ float tanh_f(float x) { return 1.0f - 2.0f / (1.0f + __expf(2.0f * x)); }
__device__ __forceinline__ float lrelu(float x)  { return fmaxf(x, 0.2f * x); }

__device__ __forceinline__ unsigned smem_u32(const void* p) {
    return (unsigned)__cvta_generic_to_shared(p);
}
__device__ __forceinline__ void ldsm_x4(unsigned& r0, unsigned& r1, unsigned& r2, unsigned& r3, unsigned a) {
    asm volatile("ldmatrix.sync.aligned.m8n8.x4.shared.b16 {%0,%1,%2,%3}, [%4];"
                 : "=r"(r0), "=r"(r1), "=r"(r2), "=r"(r3) : "r"(a));
}
__device__ __forceinline__ void ldsm_x4t(unsigned& r0, unsigned& r1, unsigned& r2, unsigned& r3, unsigned a) {
    asm volatile("ldmatrix.sync.aligned.m8n8.x4.trans.shared.b16 {%0,%1,%2,%3}, [%4];"
                 : "=r"(r0), "=r"(r1), "=r"(r2), "=r"(r3) : "r"(a));
}
__device__ __forceinline__ void mma16816(float& c0, float& c1, float& c2, float& c3,
                                         unsigned a0, unsigned a1, unsigned a2, unsigned a3,
                                         unsigned b0, unsigned b1) {
    asm volatile("mma.sync.aligned.m16n8k16.row.col.f32.f16.f16.f32 "
                 "{%0,%1,%2,%3}, {%4,%5,%6,%7}, {%8,%9}, {%0,%1,%2,%3};"
                 : "+f"(c0), "+f"(c1), "+f"(c2), "+f"(c3)
                 : "r"(a0), "r"(a1), "r"(a2), "r"(a3), "r"(b0), "r"(b1));
}
// permuted col q -> original gate row: gate = q&3, unit = q>>2
__device__ __forceinline__ int qorig(int q) { return (q & 3) * 64 + (q >> 2); }

// ================= recurrent LSTM core (K=64), tensor cores =================
// 320 thr = 10 warps: m = w>>1 (5 m16-tiles = 80 rows), nh = w&1 (128-col half).
// grid 150 x 80 seqs. W hi/lo fp16 in smem; h double-buffered; 1 sync per t.
template<int LAYER>
__global__ void __launch_bounds__(320, 1) lstm_rec_kernel(
    const float* __restrict__ x, const float* __restrict__ Wih,
    const float* __restrict__ Whh, const float* __restrict__ bih,
    const float* __restrict__ bhh)
{
    extern __shared__ char sm[];
    __half* Whi   = (__half*)sm;               // [64][264]
    __half* Wlo   = (__half*)(sm + 33792);
    __half* Hb0   = (__half*)(sm + 67584);     // [80][72]
    __half* Hb1   = (__half*)(sm + 79104);
    float* bias_s = (float*)(sm + 90624);      // [256] q-perm
    float* wih_s  = (float*)(sm + 91648);      // [256] q-perm (layer0)
    float* x_s    = (float*)(sm + 92672);      // [12][80] (layer0)

    const int tid = threadIdx.x;
    const int sb = blockIdx.x * 80;

    for (int i = tid; i < 64 * 256; i += 320) {
        int k = i >> 8, q = i & 255, orig = qorig(q);
        float wv = Whh[orig * 64 + k];
        __half hi = __float2half_rn(wv);
        Whi[k * 264 + q] = hi;
        Wlo[k * 264 + q] = __float2half_rn(wv - __half2float(hi));
    }
    if (tid < 256) {
        int orig = qorig(tid);
        bias_s[tid] = bih[orig] + bhh[orig];
        if (!LAYER) wih_s[tid] = Wih[orig];
    }
    if (!LAYER) {
        for (int i = tid; i < 960; i += 320) {
            int t = i / 80, sl = i - t * 80;
            int seq = sb + sl, b = seq / NN, n = seq - b * NN;
            x_s[i] = x[(b * TT + t) * NN + n];
        }
    }
    for (int i = tid; i < 2880; i += 320) ((unsigned*)Hb0)[i] = 0u;
    __syncthreads();

    const int w = tid >> 5, lane = tid & 31;
    const int m = w >> 1, nh = w & 1, lp = lane & 3;
    const unsigned a_off = (unsigned)(((m * 16 + (lane & 15)) * 72 + (lane >> 4) * 8) * 2);
    const unsigned b_off = (unsigned)(((lane & 15) * 264 + nh * 128 + (lane >> 4) * 8) * 2);
    const unsigned whi_b = smem_u32(Whi) + b_off;
    const unsigned wlo_b = smem_u32(Wlo) + b_off;
    const unsigned hb0 = smem_u32(Hb0) + a_off;
    const unsigned hb1 = smem_u32(Hb1) + a_off;
    const int r0 = m * 16 + (lane >> 2);

    float cst[32];
#pragma unroll
    for (int i = 0; i < 32; i++) cst[i] = 0.0f;

#pragma unroll 1
    for (int t = 0; t < TT; t++) {
        float acc[16][4];
        if (LAYER) {
            const float* xpr0 = &g_xp[((size_t)t * BNS + sb + r0) * 256];
            const float* xpr1 = xpr0 + 8 * 256;
#pragma unroll
            for (int nt = 0; nt < 16; nt++) {
                const int q0 = nh * 128 + nt * 8 + 2 * lp;
                float2 v0 = *(const float2*)&xpr0[q0];
                float2 v1 = *(const float2*)&xpr1[q0];
                acc[nt][0] = v0.x; acc[nt][1] = v0.y;
                acc[nt][2] = v1.x; acc[nt][3] = v1.y;
            }
        } else {
#pragma unroll
            for (int nt = 0; nt < 16; nt++) {
                acc[nt][0] = 0.f; acc[nt][1] = 0.f; acc[nt][2] = 0.f; acc[nt][3] = 0.f;
            }
        }
        const unsigned ha = (t & 1) ? hb1 : hb0;
        __half* Hw = (t & 1) ? Hb0 : Hb1;

#pragma unroll
        for (int kt = 0; kt < 4; kt++) {
            unsigned a0, a1, a2, a3;
            ldsm_x4(a0, a1, a2, a3, ha + kt * 32);
#pragma unroll
            for (int n16 = 0; n16 < 8; n16++) {
                const unsigned off = (unsigned)((kt * 16 * 264 + n16 * 16) * 2);
                unsigned b0, b1, b2, b3;
                ldsm_x4t(b0, b1, b2, b3, whi_b + off);
                mma16816(acc[2*n16][0], acc[2*n16][1], acc[2*n16][2], acc[2*n16][3],
                         a0, a1, a2, a3, b0, b1);
                mma16816(acc[2*n16+1][0], acc[2*n16+1][1], acc[2*n16+1][2], acc[2*n16+1][3],
                         a0, a1, a2, a3, b2, b3);
                ldsm_x4t(b0, b1, b2, b3, wlo_b + off);
                mma16816(acc[2*n16][0], acc[2*n16][1], acc[2*n16][2], acc[2*n16][3],
                         a0, a1, a2, a3, b0, b1);
                mma16816(acc[2*n16+1][0], acc[2*n16+1][1], acc[2*n16+1][2], acc[2*n16+1][3],
                         a0, a1, a2, a3, b2, b3);
            }
        }

        float xr0 = 0.f, xr1 = 0.f;
        if (!LAYER) { xr0 = x_s[t * 80 + r0]; xr1 = x_s[t * 80 + r0 + 8]; }
#pragma unroll
        for (int nt = 0; nt < 16; nt++) {
            const int q0 = nh * 128 + nt * 8 + 2 * lp;
            const float bs0 = bias_s[q0], bs1 = bias_s[q0 + 1];
#pragma unroll
            for (int rs = 0; rs < 2; rs++) {
                float g0 = acc[nt][rs * 2] + bs0;
                float g1 = acc[nt][rs * 2 + 1] + bs1;
                if (!LAYER) {
                    float xr = rs ? xr1 : xr0;
                    g0 += wih_s[q0] * xr;
                    g1 += wih_s[q0 + 1] * xr;
                }
                // even lane (lp even): gates (i,f); odd lane: gates (g,o)
                float v0 = (lane & 1) ? tanh_f(g0) : sigf(g0);
                float v1 = sigf(g1);
                float o0 = __shfl_xor_sync(0xffffffffu, v0, 1);
                float o1 = __shfl_xor_sync(0xffffffffu, v1, 1);
                if (lane & 1) {
                    const int ci = nt * 2 + rs;
                    float c = o1 * cst[ci] + o0 * v0;   // sf*c + si*tanh(g)
                    cst[ci] = c;
                    float h = v1 * tanh_f(c);           // sig(o)*tanh(c)
                    const int u = nh * 32 + nt * 2 + (lp >> 1);
                    const int r = r0 + rs * 8;
                    Hw[r * 72 + u] = __float2half_rn(h);
                    if (!LAYER)
                        g_h0h[((size_t)t * BNS + sb + r) * 64 + u] = __float2half_rn(h);
                    else if (t == TT - 1)
                        g_h[(sb + r) * 64 + u] = h;
                }
            }
        }
        __syncthreads();
    }
}

// ================= layer1 input projection: xp = h0 @ Wih1^T (q-permuted) =====
// 256 thr = 8 warps (4 m-tiles x 2 n-halves), 64 rows/block, grid 2250.
__global__ void __launch_bounds__(256) xproj_kernel(const float* __restrict__ Wih)
{
    extern __shared__ char sm[];
    __half* Whi = (__half*)sm;              // [64][264]
    __half* Wlo = (__half*)(sm + 33792);
    __half* A_s = (__half*)(sm + 67584);    // [64][72]
    const int tid = threadIdx.x;
    const size_t R0 = (size_t)blockIdx.x * 64;

    for (int i = tid; i < 64 * 256; i += 256) {
        int k = i >> 8, q = i & 255, orig = qorig(q);
        float wv = Wih[orig * 64 + k];
        __half hi = __float2half_rn(wv);
        Whi[k * 264 + q] = hi;
        Wlo[k * 264 + q] = __float2half_rn(wv - __half2float(hi));
    }
    for (int i = tid; i < 512; i += 256) {
        int row = i >> 3, c8 = (i & 7) * 8;
        *(uint4*)&A_s[row * 72 + c8] = *(const uint4*)&g_h0h[(R0 + row) * 64 + c8];
    }
    __syncthreads();

    const int w = tid >> 5, lane = tid & 31;
    const int m = w >> 1, nh = w & 1, lp = lane & 3;
    const unsigned a_b = smem_u32(A_s) + (unsigned)(((m * 16 + (lane & 15)) * 72 + (lane >> 4) * 8) * 2);
    const unsigned b_off = (unsigned)(((lane & 15) * 264 + nh * 128 + (lane >> 4) * 8) * 2);
    const unsigned whi_b = smem_u32(Whi) + b_off;
    const unsigned wlo_b = smem_u32(Wlo) + b_off;

    float acc[16][4];
#pragma unroll
    for (int i = 0; i < 16; i++) { acc[i][0]=0.f; acc[i][1]=0.f; acc[i][2]=0.f; acc[i][3]=0.f; }

#pragma unroll
    for (int kt = 0; kt < 4; kt++) {
        unsigned a0, a1, a2, a3;
        ldsm_x4(a0, a1, a2, a3, a_b + kt * 32);
#pragma unroll
        for (int n16 = 0; n16 < 8; n16++) {
            const unsigned off = (unsigned)((kt * 16 * 264 + n16 * 16) * 2);
            unsigned b0, b1, b2, b3;
            ldsm_x4t(b0, b1, b2, b3, whi_b + off);
            mma16816(acc[2*n16][0], acc[2*n16][1], acc[2*n16][2], acc[2*n16][3],
                     a0, a1, a2, a3, b0, b1);
            mma16816(acc[2*n16+1][0], acc[2*n16+1][1], acc[2*n16+1][2], acc[2*n16+1][3],
                     a0, a1, a2, a3, b2, b3);
            ldsm_x4t(b0, b1, b2, b3, wlo_b + off);
            mma16816(acc[2*n16][0], acc[2*n16][1], acc[2*n16][2], acc[2*n16][3],
                     a0, a1, a2, a3, b0, b1);
            mma16816(acc[2*n16+1][0], acc[2*n16+1][1], acc[2*n16+1][2], acc[2*n16+1][3],
                     a0, a1, a2, a3, b2, b3);
        }
    }
    const int r0 = m * 16 + (lane >> 2);
#pragma unroll
    for (int nt = 0; nt < 16; nt++) {
        const int q0 = nh * 128 + nt * 8 + 2 * lp;
#pragma unroll
        for (int rs = 0; rs < 2; rs++) {
            *(float2*)&g_xp[(R0 + r0 + rs * 8) * 256 + q0] =
                make_float2(acc[nt][rs * 2], acc[nt][rs * 2 + 1]);
        }
    }
}

// ================= GAT prep: hp(fp16) = h @ W^T, e_src, e_dst =================
__global__ void __launch_bounds__(256) gat_prep_kernel(
    const float* __restrict__ hin, const float* __restrict__ W,
    const float* __restrict__ asrc, const float* __restrict__ adst)
{
    __shared__ float W_s[64 * 65];
    __shared__ float hin_s[4][64];
    __shared__ float hp_s[4][64];
    __shared__ float as_s[64], ad_s[64];
    const int tid = threadIdx.x;
    for (int i = tid; i < 4096; i += 256) W_s[(i >> 6) * 65 + (i & 63)] = W[i];
    const int ri = tid >> 6, k = tid & 63;
    const int r = blockIdx.x * 4 + ri;
    hin_s[ri][k] = hin[r * 64 + k];
    if (tid < 64) as_s[tid] = asrc[tid];
    else if (tid < 128) ad_s[tid - 64] = adst[tid - 64];
    __syncthreads();
    float acc = 0.0f;
#pragma unroll
    for (int c = 0; c < 64; c++) acc += W_s[k * 65 + c] * hin_s[ri][c];
    g_hph[r * 64 + k] = __float2half(acc);
    hp_s[ri][k] = acc;
    __syncthreads();
    if (tid < 32) {
        int rri = tid >> 3, h = (tid >> 1) & 3, ww = tid & 1;
        const float* a = ww ? ad_s : as_s;
        float d = 0.0f;
#pragma unroll
        for (int dd = 0; dd < 16; dd++) d += hp_s[rri][h * 16 + dd] * a[h * 16 + dd];
        int rr = blockIdx.x * 4 + rri;
        if (ww) g_ed[rr * 4 + h] = d; else g_es[rr * 4 + h] = d;
    }
}

// ================= global per-(b,h) max of ed =================
__global__ void __launch_bounds__(256) gmax_kernel() {
    const int w = blockIdx.x;
    const int b = w >> 2, h = w & 3;
    __shared__ float red[8];
    const int tid = threadIdx.x;
    float m = -1e30f;
    for (int j = tid; j < NN; j += 256)
        m = fmaxf(m, g_ed[(b * NN + j) * 4 + h]);
#pragma unroll
    for (int off = 16; off; off >>= 1)
        m = fmaxf(m, __shfl_xor_sync(0xffffffffu, m, off));
    if ((tid & 31) == 0) red[tid >> 5] = m;
    __syncthreads();
    if (tid == 0) {
        float mm = red[0];
#pragma unroll
        for (int i = 1; i < 8; i++) mm = fmaxf(mm, red[i]);
        g_gmax[w] = mm;
    }
}

// ================= GAT softmax + aggregate via mma.m16n8k16 =================
#define NTJ 24
__global__ void __launch_bounds__(256, 2) gat_agg2_kernel(
    const int* __restrict__ adj, float* __restrict__ out)
{
    extern __shared__ char smc[];
    __half* hp_s = (__half*)smc;                    // [64][72]
    __half* p_s  = (__half*)(smc + 9216);           // [8][16][72]
    float* ed_s  = (float*)(smc + 27648);           // [1536][4]
    unsigned* adjm = (unsigned*)(smc + 52224);      // [64]
    float* psum_s  = (float*)(smc + 52480);         // [8][16]

    const int tid = threadIdx.x;
    const int b = blockIdx.y;
    const int i0 = blockIdx.x * 32;
    const int warp = tid >> 5, lane = tid & 31;
    const int h_w = warp & 3, seg = warp >> 2;
    const int iw0 = i0 + seg * 16;
    const int i_loc = lane >> 1, jhalf = lane & 1;
    const int i_row = iw0 + i_loc;
    const int irc = (i_row < NN) ? i_row : NN - 1;

    for (int idx = tid; idx < 1536; idx += 256) {
        float4 v = make_float4(0.f, 0.f, 0.f, 0.f);
        if (idx < NN) v = reinterpret_cast<const float4*>(g_ed)[b * NN + idx];
        reinterpret_cast<float4*>(ed_s)[idx] = v;
    }

    const float es = g_es[(b * NN + irc) * 4 + h_w];
    const float M  = lrelu(es + g_gmax[b * 4 + h_w]);

    __half* pw = p_s + warp * (16 * 72);
    const unsigned pw_b  = smem_u32(pw);
    const unsigned hps_b = smem_u32(hp_s);

    float acc[8];
#pragma unroll
    for (int i = 0; i < 8; i++) acc[i] = 0.0f;
    float psl = 0.0f;

    for (int jt = 0; jt < NTJ; jt++) {
        const int jb = jt * 64;
        __syncthreads();
        for (int k = tid; k < 512; k += 256) {
            int jl = k >> 3, co = (k & 7) * 8;
            int j = jb + jl;
            uint4 v = make_uint4(0u, 0u, 0u, 0u);
            if (j < NN) v = *reinterpret_cast<const uint4*>(&g_hph[(b * NN + j) * 64 + co]);
            *reinterpret_cast<uint4*>(&hp_s[jl * 72 + co]) = v;
        }
#pragma unroll
        for (int p = 0; p < 8; p++) {
            int word = warp * 8 + p;
            int ii = i0 + (word >> 1);
            int jj = jb + (word & 1) * 32 + lane;
            int a = (ii < NN && jj < NN) ? adj[ii * NN + jj] : 0;
            unsigned m = __ballot_sync(0xffffffffu, a > 0);
            if (lane == 0) adjm[word] = m;
        }
        __syncthreads();

        {
            unsigned mword = adjm[(seg * 16 + i_loc) * 2 + jhalf];
            const float* edp = ed_s + (jb + jhalf * 32) * 4 + h_w;
            __half2* pst = reinterpret_cast<__half2*>(pw + i_loc * 72 + jhalf * 32);
#pragma unroll
            for (int q = 0; q < 32; q += 2) {
                float m0 = (float)((mword >> q) & 1u);
                float m1 = (float)((mword >> (q + 1)) & 1u);
                float p0 = m0 * __expf(lrelu(es + edp[q * 4]) - M);
                float p1 = m1 * __expf(lrelu(es + edp[(q + 1) * 4]) - M);
                psl += p0 + p1;
                pst[q >> 1] = __floats2half2_rn(p0, p1);
            }
        }
        __syncwarp();

        const unsigned a_addr0 = pw_b + (lane & 15) * 144 + ((lane >> 4) * 8) * 2;
        const unsigned b_addr0 = hps_b + ((lane & 15) * 72 + h_w * 16 + (lane >> 4) * 8) * 2;
#pragma unroll
        for (int kt = 0; kt < 4; kt++) {
            unsigned a0, a1, a2, a3, b0, b1, b2, b3;
            ldsm_x4 (a0, a1, a2, a3, a_addr0 + kt * 32);
            ldsm_x4t(b0, b1, b2, b3, b_addr0 + kt * 16 * 144);
            mma16816(acc[0], acc[1], acc[2], acc[3], a0, a1, a2, a3, b0, b1);
            mma16816(acc[4], acc[5], acc[6], acc[7], a0, a1, a2, a3, b2, b3);
        }
    }

    psl += __shfl_xor_sync(0xffffffffu, psl, 1);
    if (jhalf == 0) psum_s[warp * 16 + i_loc] = psl;
    __syncwarp();

    const int r_lo = iw0 + (lane >> 2), r_hi = r_lo + 8;
    const float inv_lo = 1.0f / psum_s[warp * 16 + (lane >> 2)];
    const float inv_hi = 1.0f / psum_s[warp * 16 + (lane >> 2) + 8];
    const int cb = h_w * 16 + (lane & 3) * 2;
    if (r_lo < NN) {
        *reinterpret_cast<float2*>(&out[(b * NN + r_lo) * 64 + cb]) =
            make_float2(fmaxf(acc[0] * inv_lo, 0.f), fmaxf(acc[1] * inv_lo, 0.f));
        *reinterpret_cast<float2*>(&out[(b * NN + r_lo) * 64 + cb + 8]) =
            make_float2(fmaxf(acc[4] * inv_lo, 0.f), fmaxf(acc[5] * inv_lo, 0.f));
    }
    if (r_hi < NN) {
        *reinterpret_cast<float2*>(&out[(b * NN + r_hi) * 64 + cb]) =
            make_float2(fmaxf(acc[2] * inv_hi, 0.f), fmaxf(acc[3] * inv_hi, 0.f));
        *reinterpret_cast<float2*>(&out[(b * NN + r_hi) * 64 + cb + 8]) =
            make_float2(fmaxf(acc[6] * inv_hi, 0.f), fmaxf(acc[7] * inv_hi, 0.f));
    }
}

// ================= output head =================
__global__ void __launch_bounds__(256) head_kernel(
    const float* __restrict__ oW, const float* __restrict__ ob,
    float* __restrict__ out)
{
    int s = blockIdx.x * 256 + threadIdx.x;
    if (s >= BNS) return;
    int b = s / NN, n = s % NN;
    float a0 = ob[0], a1 = ob[1], a2 = ob[2];
#pragma unroll 8
    for (int c = 0; c < 64; c++) {
        float v = g_h2[s * 64 + c];
        a0 += oW[c] * v; a1 += oW[64 + c] * v; a2 += oW[128 + c] * v;
    }
    out[(b * OUTD + 0) * NN + n] = a0;
    out[(b * OUTD + 1) * NN + n] = a1;
    out[(b * OUTD + 2) * NN + n] = a2;
}

extern "C" void kernel_launch(void* const* d_in, const int* in_sizes, int n_in,
                              void* d_out, int out_size) {
    const float* x    = (const float*)d_in[0];
    const int*   adj  = (const int*)  d_in[1];
    const float* Wih0 = (const float*)d_in[2];
    const float* Whh0 = (const float*)d_in[3];
    const float* bih0 = (const float*)d_in[4];
    const float* bhh0 = (const float*)d_in[5];
    const float* Wih1 = (const float*)d_in[6];
    const float* Whh1 = (const float*)d_in[7];
    const float* bih1 = (const float*)d_in[8];
    const float* bhh1 = (const float*)d_in[9];
    const float* g0W  = (const float*)d_in[10];
    const float* g0as = (const float*)d_in[11];
    const float* g0ad = (const float*)d_in[12];
    const float* g1W  = (const float*)d_in[13];
    const float* g1as = (const float*)d_in[14];
    const float* g1ad = (const float*)d_in[15];
    const float* outW = (const float*)d_in[16];
    const float* outb = (const float*)d_in[17];
    float* out = (float*)d_out;

    cudaFuncSetAttribute(lstm_rec_kernel<0>, cudaFuncAttributeMaxDynamicSharedMemorySize, 96512);
    cudaFuncSetAttribute(lstm_rec_kernel<1>, cudaFuncAttributeMaxDynamicSharedMemorySize, 96512);
    cudaFuncSetAttribute(xproj_kernel,       cudaFuncAttributeMaxDynamicSharedMemorySize, 76800);
    cudaFuncSetAttribute(gat_agg2_kernel,    cudaFuncAttributeMaxDynamicSharedMemorySize, 52992);

    float* g_h_p;  cudaGetSymbolAddress((void**)&g_h_p,  g_h);
    float* g_ho_p; cudaGetSymbolAddress((void**)&g_ho_p, g_ho);
    float* g_h2_p; cudaGetSymbolAddress((void**)&g_h2_p, g_h2);

    lstm_rec_kernel<0><<<150, 320, 96512>>>(x, Wih0, Whh0, bih0, bhh0);
    xproj_kernel<<<2250, 256, 76800>>>(Wih1);
    lstm_rec_kernel<1><<<150, 320, 96512>>>(x, Wih1, Whh1, bih1, bhh1);

    gat_prep_kernel<<<3000, 256>>>(g_h_p, g0W, g0as, g0ad);
    gmax_kernel<<<32, 256>>>();
    gat_agg2_kernel<<<dim3(47, 8), 256, 52992>>>(adj, g_ho_p);

    gat_prep_kernel<<<3000, 256>>>(g_ho_p, g1W, g1as, g1ad);
    gmax_kernel<<<32, 256>>>();
    gat_agg2_kernel<<<dim3(47, 8), 256, 52992>>>(adj, g_h2_p);

    head_kernel<<<47, 256>>>(outW, outb, out);
}

// round 14
// speedup vs baseline: 1.2963x; 1.2963x over previous
#include <cuda_runtime.h>
#include <cuda_fp16.h>
#include <cuda_bf16.h>

#define BB 8
#define TT 12
#define NN 1500
#define BNS 12000
#define OUTD 3

// ---- scratch (device globals, no runtime alloc) ----
static __device__ __half g_h0h[(size_t)TT * BNS * 64];   // layer0 hidden fp16
static __device__ float  g_h  [BNS * 64];
static __device__ __half g_hph[BNS * 64];
static __device__ float  g_es [BNS * 4];
static __device__ float  g_ed [BNS * 4];
static __device__ float  g_gmax[BB * 4];
static __device__ float  g_ho [BNS * 64];
static __device__ float  g_h2 [BNS * 64];
static __device__ float  g_scr[64];

__device__ __forceinline__ float sigf(float x)   { return 1.0f / (1.0f + __expf(-x)); }
__device__ __forceinline__ float tanh_f(float x) { return 1.0f - 2.0f / (1.0f + __expf(2.0f * x)); }
__device__ __forceinline__ float lrelu(float x)  { return fmaxf(x, 0.2f * x); }

__device__ __forceinline__ unsigned smem_u32(const void* p) {
    return (unsigned)__cvta_generic_to_shared(p);
}
__device__ __forceinline__ void ldsm_x4(unsigned& r0, unsigned& r1, unsigned& r2, unsigned& r3, unsigned a) {
    asm volatile("ldmatrix.sync.aligned.m8n8.x4.shared.b16 {%0,%1,%2,%3}, [%4];"
                 : "=r"(r0), "=r"(r1), "=r"(r2), "=r"(r3) : "r"(a));
}
__device__ __forceinline__ void ldsm_x4t(unsigned& r0, unsigned& r1, unsigned& r2, unsigned& r3, unsigned a) {
    asm volatile("ldmatrix.sync.aligned.m8n8.x4.trans.shared.b16 {%0,%1,%2,%3}, [%4];"
                 : "=r"(r0), "=r"(r1), "=r"(r2), "=r"(r3) : "r"(a));
}
__device__ __forceinline__ void mma16816(float& c0, float& c1, float& c2, float& c3,
                                         unsigned a0, unsigned a1, unsigned a2, unsigned a3,
                                         unsigned b0, unsigned b1) {
    asm volatile("mma.sync.aligned.m16n8k16.row.col.f32.f16.f16.f32 "
                 "{%0,%1,%2,%3}, {%4,%5,%6,%7}, {%8,%9}, {%0,%1,%2,%3};"
                 : "+f"(c0), "+f"(c1), "+f"(c2), "+f"(c3)
                 : "r"(a0), "r"(a1), "r"(a2), "r"(a3), "r"(b0), "r"(b1));
}
// permuted col q -> original gate row: gate = q&3, unit = q>>2
__device__ __forceinline__ int qorig(int q) { return (q & 3) * 64 + (q >> 2); }

__global__ void dummy_kernel() { g_scr[threadIdx.x] = 0.0f; }

// ================= fused tensor-core LSTM =================
// LAYER0: K=64 (recurrent h), x folded in epilogue.
// LAYER1: K=128 = [h1 (recurrent); h0 (staged per t from g_h0h)]. No g_xp.
// 320 thr = 10 warps: m = w>>1 (5 m16-tiles = 80 rows), nh = w&1 (128-col half).
// grid 150 x 80 seqs; t-loop NOT unrolled (I$-resident body).
template<int LAYER>
__global__ void __launch_bounds__(320, 1) lstm_fused_kernel(
    const float* __restrict__ x, const float* __restrict__ Wih,
    const float* __restrict__ Whh, const float* __restrict__ bih,
    const float* __restrict__ bhh)
{
    constexpr int KT = LAYER ? 8 : 4;
    extern __shared__ char sm[];
    __half* Whi   = (__half*)sm;                 // [KT*16][264]
    __half* Wlo   = (__half*)(sm + 67584);
    __half* Hb0   = (__half*)(sm + 135168);      // [80][72]
    __half* Hb1   = (__half*)(sm + 146688);
    __half* H0    = (__half*)(sm + 158208);      // [80][72] layer1 input h0
    float* bias_s = (float*)(sm + 169728);       // [256] q-perm
    float* wih_s  = (float*)(sm + 170752);       // [256] q-perm (layer0)
    float* x_s    = (float*)(sm + 171776);       // [12][80] (layer0)

    const int tid = threadIdx.x;
    const int sb = blockIdx.x * 80;

    for (int i = tid; i < KT * 16 * 256; i += 320) {
        int k = i >> 8, q = i & 255, orig = qorig(q);
        float wv = (LAYER && k >= 64) ? Wih[orig * 64 + (k - 64)] : Whh[orig * 64 + k];
        __half hi = __float2half_rn(wv);
        Whi[k * 264 + q] = hi;
        Wlo[k * 264 + q] = __float2half_rn(wv - __half2float(hi));
    }
    if (tid < 256) {
        int orig = qorig(tid);
        bias_s[tid] = bih[orig] + bhh[orig];
        if (!LAYER) wih_s[tid] = Wih[orig];
    }
    if (!LAYER) {
        for (int i = tid; i < 960; i += 320) {
            int t = i / 80, sl = i - t * 80;
            int seq = sb + sl, b = seq / NN, n = seq - b * NN;
            x_s[i] = x[(b * TT + t) * NN + n];
        }
    }
    for (int i = tid; i < 2880; i += 320) ((unsigned*)Hb0)[i] = 0u;
    __syncthreads();

    const int w = tid >> 5, lane = tid & 31;
    const int m = w >> 1, nh = w & 1, lp = lane & 3;
    const unsigned a_off = (unsigned)(((m * 16 + (lane & 15)) * 72 + (lane >> 4) * 8) * 2);
    const unsigned b_off = (unsigned)(((lane & 15) * 264 + nh * 128 + (lane >> 4) * 8) * 2);
    const unsigned whi_b = smem_u32(Whi) + b_off;
    const unsigned wlo_b = smem_u32(Wlo) + b_off;
    const unsigned hb0 = smem_u32(Hb0) + a_off;
    const unsigned hb1 = smem_u32(Hb1) + a_off;
    const unsigned h0b = smem_u32(H0) + a_off;
    const int r0 = m * 16 + (lane >> 2);

    float cst[32];
#pragma unroll
    for (int i = 0; i < 32; i++) cst[i] = 0.0f;

#pragma unroll 1
    for (int t = 0; t < TT; t++) {
        if (LAYER) {
            for (int i = tid; i < 640; i += 320) {
                int row = i >> 3, c8 = (i & 7) * 8;
                *(uint4*)&H0[row * 72 + c8] =
                    *(const uint4*)&g_h0h[((size_t)t * BNS + sb + row) * 64 + c8];
            }
            __syncthreads();
        }
        float acc[16][4];
#pragma unroll
        for (int i = 0; i < 16; i++) {
            acc[i][0] = 0.f; acc[i][1] = 0.f; acc[i][2] = 0.f; acc[i][3] = 0.f;
        }
        const unsigned ha = (t & 1) ? hb1 : hb0;
        __half* Hw = (t & 1) ? Hb0 : Hb1;

#pragma unroll
        for (int kt = 0; kt < KT; kt++) {
            unsigned a0, a1, a2, a3;
            const unsigned ab = (kt < 4 ? ha : h0b) + (unsigned)(((kt & 3) * 16) * 2);
            ldsm_x4(a0, a1, a2, a3, ab);
#pragma unroll
            for (int n16 = 0; n16 < 8; n16++) {
                const unsigned off = (unsigned)((kt * 16 * 264 + n16 * 16) * 2);
                unsigned b0, b1, b2, b3;
                ldsm_x4t(b0, b1, b2, b3, whi_b + off);
                mma16816(acc[2*n16][0], acc[2*n16][1], acc[2*n16][2], acc[2*n16][3],
                         a0, a1, a2, a3, b0, b1);
                mma16816(acc[2*n16+1][0], acc[2*n16+1][1], acc[2*n16+1][2], acc[2*n16+1][3],
                         a0, a1, a2, a3, b2, b3);
                ldsm_x4t(b0, b1, b2, b3, wlo_b + off);
                mma16816(acc[2*n16][0], acc[2*n16][1], acc[2*n16][2], acc[2*n16][3],
                         a0, a1, a2, a3, b0, b1);
                mma16816(acc[2*n16+1][0], acc[2*n16+1][1], acc[2*n16+1][2], acc[2*n16+1][3],
                         a0, a1, a2, a3, b2, b3);
            }
        }

        float xr0 = 0.f, xr1 = 0.f;
        if (!LAYER) { xr0 = x_s[t * 80 + r0]; xr1 = x_s[t * 80 + r0 + 8]; }
#pragma unroll
        for (int nt = 0; nt < 16; nt++) {
            const int q0 = nh * 128 + nt * 8 + 2 * lp;
            const float bs0 = bias_s[q0], bs1 = bias_s[q0 + 1];
#pragma unroll
            for (int rs = 0; rs < 2; rs++) {
                float g0 = acc[nt][rs * 2] + bs0;
                float g1 = acc[nt][rs * 2 + 1] + bs1;
                if (!LAYER) {
                    float xr = rs ? xr1 : xr0;
                    g0 += wih_s[q0] * xr;
                    g1 += wih_s[q0 + 1] * xr;
                }
                float v0 = (lane & 1) ? tanh_f(g0) : sigf(g0);
                float v1 = sigf(g1);
                float o0 = __shfl_xor_sync(0xffffffffu, v0, 1);
                float o1 = __shfl_xor_sync(0xffffffffu, v1, 1);
                if (lane & 1) {
                    const int ci = nt * 2 + rs;
                    float c = o1 * cst[ci] + o0 * v0;
                    cst[ci] = c;
                    float h = v1 * tanh_f(c);
                    const int u = nh * 32 + nt * 2 + (lp >> 1);
                    const int r = r0 + rs * 8;
                    Hw[r * 72 + u] = __float2half_rn(h);
                    if (!LAYER)
                        g_h0h[((size_t)t * BNS + sb + r) * 64 + u] = __float2half_rn(h);
                    else if (t == TT - 1)
                        g_h[(sb + r) * 64 + u] = h;
                }
            }
        }
        __syncthreads();
    }
}

// ================= GAT prep: hp(fp16) = h @ W^T, e_src, e_dst =================
__global__ void __launch_bounds__(256) gat_prep_kernel(
    const float* __restrict__ hin, const float* __restrict__ W,
    const float* __restrict__ asrc, const float* __restrict__ adst)
{
    __shared__ float W_s[64 * 65];
    __shared__ float hin_s[4][64];
    __shared__ float hp_s[4][64];
    __shared__ float as_s[64], ad_s[64];
    const int tid = threadIdx.x;
    for (int i = tid; i < 4096; i += 256) W_s[(i >> 6) * 65 + (i & 63)] = W[i];
    const int ri = tid >> 6, k = tid & 63;
    const int r = blockIdx.x * 4 + ri;
    hin_s[ri][k] = hin[r * 64 + k];
    if (tid < 64) as_s[tid] = asrc[tid];
    else if (tid < 128) ad_s[tid - 64] = adst[tid - 64];
    __syncthreads();
    float acc = 0.0f;
#pragma unroll
    for (int c = 0; c < 64; c++) acc += W_s[k * 65 + c] * hin_s[ri][c];
    g_hph[r * 64 + k] = __float2half(acc);
    hp_s[ri][k] = acc;
    __syncthreads();
    if (tid < 32) {
        int rri = tid >> 3, h = (tid >> 1) & 3, ww = tid & 1;
        const float* a = ww ? ad_s : as_s;
        float d = 0.0f;
#pragma unroll
        for (int dd = 0; dd < 16; dd++) d += hp_s[rri][h * 16 + dd] * a[h * 16 + dd];
        int rr = blockIdx.x * 4 + rri;
        if (ww) g_ed[rr * 4 + h] = d; else g_es[rr * 4 + h] = d;
    }
}

// ================= global per-(b,h) max of ed =================
__global__ void __launch_bounds__(256) gmax_kernel() {
    const int w = blockIdx.x;
    const int b = w >> 2, h = w & 3;
    __shared__ float red[8];
    const int tid = threadIdx.x;
    float m = -1e30f;
    for (int j = tid; j < NN; j += 256)
        m = fmaxf(m, g_ed[(b * NN + j) * 4 + h]);
#pragma unroll
    for (int off = 16; off; off >>= 1)
        m = fmaxf(m, __shfl_xor_sync(0xffffffffu, m, off));
    if ((tid & 31) == 0) red[tid >> 5] = m;
    __syncthreads();
    if (tid == 0) {
        float mm = red[0];
#pragma unroll
        for (int i = 1; i < 8; i++) mm = fmaxf(mm, red[i]);
        g_gmax[w] = mm;
    }
}

// ================= GAT softmax + aggregate via mma.m16n8k16 =================
#define NTJ 24
__global__ void __launch_bounds__(256, 2) gat_agg2_kernel(
    const int* __restrict__ adj, float* __restrict__ out)
{
    extern __shared__ char smc[];
    __half* hp_s = (__half*)smc;                    // [64][72]
    __half* p_s  = (__half*)(smc + 9216);           // [8][16][72]
    float* ed_s  = (float*)(smc + 27648);           // [1536][4]
    unsigned* adjm = (unsigned*)(smc + 52224);      // [64]
    float* psum_s  = (float*)(smc + 52480);         // [8][16]

    const int tid = threadIdx.x;
    const int b = blockIdx.y;
    const int i0 = blockIdx.x * 32;
    const int warp = tid >> 5, lane = tid & 31;
    const int h_w = warp & 3, seg = warp >> 2;
    const int iw0 = i0 + seg * 16;
    const int i_loc = lane >> 1, jhalf = lane & 1;
    const int i_row = iw0 + i_loc;
    const int irc = (i_row < NN) ? i_row : NN - 1;

    for (int idx = tid; idx < 1536; idx += 256) {
        float4 v = make_float4(0.f, 0.f, 0.f, 0.f);
        if (idx < NN) v = reinterpret_cast<const float4*>(g_ed)[b * NN + idx];
        reinterpret_cast<float4*>(ed_s)[idx] = v;
    }

    const float es = g_es[(b * NN + irc) * 4 + h_w];
    const float M  = lrelu(es + g_gmax[b * 4 + h_w]);

    __half* pw = p_s + warp * (16 * 72);
    const unsigned pw_b  = smem_u32(pw);
    const unsigned hps_b = smem_u32(hp_s);

    float acc[8];
#pragma unroll
    for (int i = 0; i < 8; i++) acc[i] = 0.0f;
    float psl = 0.0f;

    for (int jt = 0; jt < NTJ; jt++) {
        const int jb = jt * 64;
        __syncthreads();
        for (int k = tid; k < 512; k += 256) {
            int jl = k >> 3, co = (k & 7) * 8;
            int j = jb + jl;
            uint4 v = make_uint4(0u, 0u, 0u, 0u);
            if (j < NN) v = *reinterpret_cast<const uint4*>(&g_hph[(b * NN + j) * 64 + co]);
            *reinterpret_cast<uint4*>(&hp_s[jl * 72 + co]) = v;
        }
#pragma unroll
        for (int p = 0; p < 8; p++) {
            int word = warp * 8 + p;
            int ii = i0 + (word >> 1);
            int jj = jb + (word & 1) * 32 + lane;
            int a = (ii < NN && jj < NN) ? adj[ii * NN + jj] : 0;
            unsigned m = __ballot_sync(0xffffffffu, a > 0);
            if (lane == 0) adjm[word] = m;
        }
        __syncthreads();

        {
            unsigned mword = adjm[(seg * 16 + i_loc) * 2 + jhalf];
            const float* edp = ed_s + (jb + jhalf * 32) * 4 + h_w;
            __half2* pst = reinterpret_cast<__half2*>(pw + i_loc * 72 + jhalf * 32);
#pragma unroll
            for (int q = 0; q < 32; q += 2) {
                float m0 = (float)((mword >> q) & 1u);
                float m1 = (float)((mword >> (q + 1)) & 1u);
                float p0 = m0 * __expf(lrelu(es + edp[q * 4]) - M);
                float p1 = m1 * __expf(lrelu(es + edp[(q + 1) * 4]) - M);
                psl += p0 + p1;
                pst[q >> 1] = __floats2half2_rn(p0, p1);
            }
        }
        __syncwarp();

        const unsigned a_addr0 = pw_b + (lane & 15) * 144 + ((lane >> 4) * 8) * 2;
        const unsigned b_addr0 = hps_b + ((lane & 15) * 72 + h_w * 16 + (lane >> 4) * 8) * 2;
#pragma unroll
        for (int kt = 0; kt < 4; kt++) {
            unsigned a0, a1, a2, a3, b0, b1, b2, b3;
            ldsm_x4 (a0, a1, a2, a3, a_addr0 + kt * 32);
            ldsm_x4t(b0, b1, b2, b3, b_addr0 + kt * 16 * 144);
            mma16816(acc[0], acc[1], acc[2], acc[3], a0, a1, a2, a3, b0, b1);
            mma16816(acc[4], acc[5], acc[6], acc[7], a0, a1, a2, a3, b2, b3);
        }
    }

    psl += __shfl_xor_sync(0xffffffffu, psl, 1);
    if (jhalf == 0) psum_s[warp * 16 + i_loc] = psl;
    __syncwarp();

    const int r_lo = iw0 + (lane >> 2), r_hi = r_lo + 8;
    const float inv_lo = 1.0f / psum_s[warp * 16 + (lane >> 2)];
    const float inv_hi = 1.0f / psum_s[warp * 16 + (lane >> 2) + 8];
    const int cb = h_w * 16 + (lane & 3) * 2;
    if (r_lo < NN) {
        *reinterpret_cast<float2*>(&out[(b * NN + r_lo) * 64 + cb]) =
            make_float2(fmaxf(acc[0] * inv_lo, 0.f), fmaxf(acc[1] * inv_lo, 0.f));
        *reinterpret_cast<float2*>(&out[(b * NN + r_lo) * 64 + cb + 8]) =
            make_float2(fmaxf(acc[4] * inv_lo, 0.f), fmaxf(acc[5] * inv_lo, 0.f));
    }
    if (r_hi < NN) {
        *reinterpret_cast<float2*>(&out[(b * NN + r_hi) * 64 + cb]) =
            make_float2(fmaxf(acc[2] * inv_hi, 0.f), fmaxf(acc[3] * inv_hi, 0.f));
        *reinterpret_cast<float2*>(&out[(b * NN + r_hi) * 64 + cb + 8]) =
            make_float2(fmaxf(acc[6] * inv_hi, 0.f), fmaxf(acc[7] * inv_hi, 0.f));
    }
}

// ================= output head =================
__global__ void __launch_bounds__(256) head_kernel(
    const float* __restrict__ oW, const float* __restrict__ ob,
    float* __restrict__ out)
{
    int s = blockIdx.x * 256 + threadIdx.x;
    if (s >= BNS) return;
    int b = s / NN, n = s % NN;
    float a0 = ob[0], a1 = ob[1], a2 = ob[2];
#pragma unroll 8
    for (int c = 0; c < 64; c++) {
        float v = g_h2[s * 64 + c];
        a0 += oW[c] * v; a1 += oW[64 + c] * v; a2 += oW[128 + c] * v;
    }
    out[(b * OUTD + 0) * NN + n] = a0;
    out[(b * OUTD + 1) * NN + n] = a1;
    out[(b * OUTD + 2) * NN + n] = a2;
}

extern "C" void kernel_launch(void* const* d_in, const int* in_sizes, int n_in,
                              void* d_out, int out_size) {
    const float* x    = (const float*)d_in[0];
    const int*   adj  = (const int*)  d_in[1];
    const float* Wih0 = (const float*)d_in[2];
    const float* Whh0 = (const float*)d_in[3];
    const float* bih0 = (const float*)d_in[4];
    const float* bhh0 = (const float*)d_in[5];
    const float* Wih1 = (const float*)d_in[6];
    const float* Whh1 = (const float*)d_in[7];
    const float* bih1 = (const float*)d_in[8];
    const float* bhh1 = (const float*)d_in[9];
    const float* g0W  = (const float*)d_in[10];
    const float* g0as = (const float*)d_in[11];
    const float* g0ad = (const float*)d_in[12];
    const float* g1W  = (const float*)d_in[13];
    const float* g1as = (const float*)d_in[14];
    const float* g1ad = (const float*)d_in[15];
    const float* outW = (const float*)d_in[16];
    const float* outb = (const float*)d_in[17];
    float* out = (float*)d_out;

    cudaFuncSetAttribute(lstm_fused_kernel<0>, cudaFuncAttributeMaxDynamicSharedMemorySize, 175616);
    cudaFuncSetAttribute(lstm_fused_kernel<1>, cudaFuncAttributeMaxDynamicSharedMemorySize, 175616);
    cudaFuncSetAttribute(gat_agg2_kernel,      cudaFuncAttributeMaxDynamicSharedMemorySize, 52992);

    float* g_h_p;  cudaGetSymbolAddress((void**)&g_h_p,  g_h);
    float* g_ho_p; cudaGetSymbolAddress((void**)&g_ho_p, g_ho);
    float* g_h2_p; cudaGetSymbolAddress((void**)&g_h2_p, g_h2);

    // launches 1-3: lstm0 + two dummies, so the fused lstm1 is launch #4
    // (the ncu capture in this harness consistently profiles launch #4).
    lstm_fused_kernel<0><<<150, 320, 175616>>>(x, Wih0, Whh0, bih0, bhh0);
    dummy_kernel<<<1, 64>>>();
    dummy_kernel<<<1, 64>>>();
    lstm_fused_kernel<1><<<150, 320, 175616>>>(x, Wih1, Whh1, bih1, bhh1);

    gat_prep_kernel<<<3000, 256>>>(g_h_p, g0W, g0as, g0ad);
    gmax_kernel<<<32, 256>>>();
    gat_agg2_kernel<<<dim3(47, 8), 256, 52992>>>(adj, g_ho_p);

    gat_prep_kernel<<<3000, 256>>>(g_ho_p, g1W, g1as, g1ad);
    gmax_kernel<<<32, 256>>>();
    gat_agg2_kernel<<<dim3(47, 8), 256, 52992>>>(adj, g_h2_p);

    head_kernel<<<47, 256>>>(outW, outb, out);
}

// round 15
// speedup vs baseline: 1.6125x; 1.2439x over previous
#include <cuda_runtime.h>
#include <cuda_fp16.h>
#include <cuda_bf16.h>

#define BB 8
#define TT 12
#define NN 1500
#define BNS 12000
#define OUTD 3

// ---- scratch (device globals, no runtime alloc) ----
static __device__ __half g_h0h[(size_t)TT * BNS * 64];   // layer0 hidden fp16
static __device__ float  g_h  [BNS * 64];
static __device__ __half g_hph[BNS * 64];
static __device__ float  g_es [BNS * 4];
static __device__ float  g_ed [BNS * 4];
static __device__ float  g_gmax[BB * 4];
static __device__ float  g_ho [BNS * 64];
static __device__ float  g_h2 [BNS * 64];
static __device__ float  g_scr[64];

__device__ __forceinline__ float sigf(float x)   { return 1.0f / (1.0f + __expf(-x)); }
__device__ __forceinline__ float tanh_f(float x) { return 1.0f - 2.0f / (1.0f + __expf(2.0f * x)); }
__device__ __forceinline__ float lrelu(float x)  { return fmaxf(x, 0.2f * x); }

__device__ __forceinline__ unsigned smem_u32(const void* p) {
    return (unsigned)__cvta_generic_to_shared(p);
}
__device__ __forceinline__ void ldsm_x4(unsigned& r0, unsigned& r1, unsigned& r2, unsigned& r3, unsigned a) {
    asm volatile("ldmatrix.sync.aligned.m8n8.x4.shared.b16 {%0,%1,%2,%3}, [%4];"
                 : "=r"(r0), "=r"(r1), "=r"(r2), "=r"(r3) : "r"(a));
}
__device__ __forceinline__ void ldsm_x4t(unsigned& r0, unsigned& r1, unsigned& r2, unsigned& r3, unsigned a) {
    asm volatile("ldmatrix.sync.aligned.m8n8.x4.trans.shared.b16 {%0,%1,%2,%3}, [%4];"
                 : "=r"(r0), "=r"(r1), "=r"(r2), "=r"(r3) : "r"(a));
}
__device__ __forceinline__ void mma16816(float& c0, float& c1, float& c2, float& c3,
                                         unsigned a0, unsigned a1, unsigned a2, unsigned a3,
                                         unsigned b0, unsigned b1) {
    asm volatile("mma.sync.aligned.m16n8k16.row.col.f32.f16.f16.f32 "
                 "{%0,%1,%2,%3}, {%4,%5,%6,%7}, {%8,%9}, {%0,%1,%2,%3};"
                 : "+f"(c0), "+f"(c1), "+f"(c2), "+f"(c3)
                 : "r"(a0), "r"(a1), "r"(a2), "r"(a3), "r"(b0), "r"(b1));
}
// permuted col q -> original gate row: gate = q&3, unit = q>>2
__device__ __forceinline__ int qorig(int q) { return (q & 3) * 64 + (q >> 2); }

__global__ void dummy_kernel() { g_scr[threadIdx.x] = 0.0f; }

// ================= fused tensor-core LSTM =================
// LAYER0: K=64 (recurrent h), x folded in epilogue.
// LAYER1: K=128 = [h1 (recurrent); h0 (staged per t from g_h0h)].
// 640 thr = 20 warps: m = w>>2 (5 m16-tiles = 80 rows), nq = w&3 (64-col quarter).
// grid 150 x 80 seqs; t-loop NOT unrolled (I$-resident body).
template<int LAYER>
__global__ void __launch_bounds__(640, 1) lstm_fused_kernel(
    const float* __restrict__ x, const float* __restrict__ Wih,
    const float* __restrict__ Whh, const float* __restrict__ bih,
    const float* __restrict__ bhh)
{
    constexpr int KT = LAYER ? 8 : 4;
    extern __shared__ char sm[];
    __half* Whi   = (__half*)sm;                 // [KT*16][264]
    __half* Wlo   = (__half*)(sm + 67584);
    __half* Hb0   = (__half*)(sm + 135168);      // [80][72]
    __half* Hb1   = (__half*)(sm + 146688);
    __half* H0    = (__half*)(sm + 158208);      // [80][72] layer1 input h0
    float* bias_s = (float*)(sm + 169728);       // [256] q-perm
    float* wih_s  = (float*)(sm + 170752);       // [256] q-perm (layer0)
    float* x_s    = (float*)(sm + 171776);       // [12][80] (layer0)

    const int tid = threadIdx.x;
    const int sb = blockIdx.x * 80;

    for (int i = tid; i < KT * 16 * 256; i += 640) {
        int k = i >> 8, q = i & 255, orig = qorig(q);
        float wv = (LAYER && k >= 64) ? Wih[orig * 64 + (k - 64)] : Whh[orig * 64 + k];
        __half hi = __float2half_rn(wv);
        Whi[k * 264 + q] = hi;
        Wlo[k * 264 + q] = __float2half_rn(wv - __half2float(hi));
    }
    if (tid < 256) {
        int orig = qorig(tid);
        bias_s[tid] = bih[orig] + bhh[orig];
        if (!LAYER) wih_s[tid] = Wih[orig];
    }
    if (!LAYER) {
        for (int i = tid; i < 960; i += 640) {
            int t = i / 80, sl = i - t * 80;
            int seq = sb + sl, b = seq / NN, n = seq - b * NN;
            x_s[i] = x[(b * TT + t) * NN + n];
        }
    }
    for (int i = tid; i < 2880; i += 640) ((unsigned*)Hb0)[i] = 0u;
    __syncthreads();

    const int w = tid >> 5, lane = tid & 31;
    const int m = w >> 2, nq = w & 3, lp = lane & 3;
    const unsigned a_off = (unsigned)(((m * 16 + (lane & 15)) * 72 + (lane >> 4) * 8) * 2);
    const unsigned b_off = (unsigned)(((lane & 15) * 264 + nq * 64 + (lane >> 4) * 8) * 2);
    const unsigned whi_b = smem_u32(Whi) + b_off;
    const unsigned wlo_b = smem_u32(Wlo) + b_off;
    const unsigned hb0 = smem_u32(Hb0) + a_off;
    const unsigned hb1 = smem_u32(Hb1) + a_off;
    const unsigned h0b = smem_u32(H0) + a_off;
    const int r0 = m * 16 + (lane >> 2);

    float cst[16];
#pragma unroll
    for (int i = 0; i < 16; i++) cst[i] = 0.0f;

#pragma unroll 1
    for (int t = 0; t < TT; t++) {
        if (LAYER) {
            for (int i = tid; i < 640; i += 640) {
                int row = i >> 3, c8 = (i & 7) * 8;
                *(uint4*)&H0[row * 72 + c8] =
                    *(const uint4*)&g_h0h[((size_t)t * BNS + sb + row) * 64 + c8];
            }
            __syncthreads();
        }
        float acc[8][4];
#pragma unroll
        for (int i = 0; i < 8; i++) {
            acc[i][0] = 0.f; acc[i][1] = 0.f; acc[i][2] = 0.f; acc[i][3] = 0.f;
        }
        const unsigned ha = (t & 1) ? hb1 : hb0;
        __half* Hw = (t & 1) ? Hb0 : Hb1;

#pragma unroll
        for (int kt = 0; kt < KT; kt++) {
            unsigned a0, a1, a2, a3;
            const unsigned ab = (kt < 4 ? ha : h0b) + (unsigned)(((kt & 3) * 16) * 2);
            ldsm_x4(a0, a1, a2, a3, ab);
#pragma unroll
            for (int n16 = 0; n16 < 4; n16++) {
                const unsigned off = (unsigned)((kt * 16 * 264 + n16 * 16) * 2);
                unsigned b0, b1, b2, b3;
                ldsm_x4t(b0, b1, b2, b3, whi_b + off);
                mma16816(acc[2*n16][0], acc[2*n16][1], acc[2*n16][2], acc[2*n16][3],
                         a0, a1, a2, a3, b0, b1);
                mma16816(acc[2*n16+1][0], acc[2*n16+1][1], acc[2*n16+1][2], acc[2*n16+1][3],
                         a0, a1, a2, a3, b2, b3);
                ldsm_x4t(b0, b1, b2, b3, wlo_b + off);
                mma16816(acc[2*n16][0], acc[2*n16][1], acc[2*n16][2], acc[2*n16][3],
                         a0, a1, a2, a3, b0, b1);
                mma16816(acc[2*n16+1][0], acc[2*n16+1][1], acc[2*n16+1][2], acc[2*n16+1][3],
                         a0, a1, a2, a3, b2, b3);
            }
        }

        float xr0 = 0.f, xr1 = 0.f;
        if (!LAYER) { xr0 = x_s[t * 80 + r0]; xr1 = x_s[t * 80 + r0 + 8]; }
#pragma unroll
        for (int nt = 0; nt < 8; nt++) {
            const int q0 = nq * 64 + nt * 8 + 2 * lp;
            const float bs0 = bias_s[q0], bs1 = bias_s[q0 + 1];
#pragma unroll
            for (int rs = 0; rs < 2; rs++) {
                float g0 = acc[nt][rs * 2] + bs0;
                float g1 = acc[nt][rs * 2 + 1] + bs1;
                if (!LAYER) {
                    float xr = rs ? xr1 : xr0;
                    g0 += wih_s[q0] * xr;
                    g1 += wih_s[q0 + 1] * xr;
                }
                float v0 = (lane & 1) ? tanh_f(g0) : sigf(g0);
                float v1 = sigf(g1);
                float o0 = __shfl_xor_sync(0xffffffffu, v0, 1);
                float o1 = __shfl_xor_sync(0xffffffffu, v1, 1);
                if (lane & 1) {
                    const int ci = nt * 2 + rs;
                    float c = o1 * cst[ci] + o0 * v0;
                    cst[ci] = c;
                    float h = v1 * tanh_f(c);
                    const int u = nq * 16 + nt * 2 + (lp >> 1);
                    const int r = r0 + rs * 8;
                    Hw[r * 72 + u] = __float2half_rn(h);
                    if (!LAYER)
                        g_h0h[((size_t)t * BNS + sb + r) * 64 + u] = __float2half_rn(h);
                    else if (t == TT - 1)
                        g_h[(sb + r) * 64 + u] = h;
                }
            }
        }
        __syncthreads();
    }
}

// ================= GAT prep: hp(fp16) = h @ W^T, e_src, e_dst =================
__global__ void __launch_bounds__(256) gat_prep_kernel(
    const float* __restrict__ hin, const float* __restrict__ W,
    const float* __restrict__ asrc, const float* __restrict__ adst)
{
    __shared__ float W_s[64 * 65];
    __shared__ float hin_s[4][64];
    __shared__ float hp_s[4][64];
    __shared__ float as_s[64], ad_s[64];
    const int tid = threadIdx.x;
    for (int i = tid; i < 4096; i += 256) W_s[(i >> 6) * 65 + (i & 63)] = W[i];
    const int ri = tid >> 6, k = tid & 63;
    const int r = blockIdx.x * 4 + ri;
    hin_s[ri][k] = hin[r * 64 + k];
    if (tid < 64) as_s[tid] = asrc[tid];
    else if (tid < 128) ad_s[tid - 64] = adst[tid - 64];
    __syncthreads();
    float acc = 0.0f;
#pragma unroll
    for (int c = 0; c < 64; c++) acc += W_s[k * 65 + c] * hin_s[ri][c];
    g_hph[r * 64 + k] = __float2half(acc);
    hp_s[ri][k] = acc;
    __syncthreads();
    if (tid < 32) {
        int rri = tid >> 3, h = (tid >> 1) & 3, ww = tid & 1;
        const float* a = ww ? ad_s : as_s;
        float d = 0.0f;
#pragma unroll
        for (int dd = 0; dd < 16; dd++) d += hp_s[rri][h * 16 + dd] * a[h * 16 + dd];
        int rr = blockIdx.x * 4 + rri;
        if (ww) g_ed[rr * 4 + h] = d; else g_es[rr * 4 + h] = d;
    }
}

// ================= global per-(b,h) max of ed =================
__global__ void __launch_bounds__(256) gmax_kernel() {
    const int w = blockIdx.x;
    const int b = w >> 2, h = w & 3;
    __shared__ float red[8];
    const int tid = threadIdx.x;
    float m = -1e30f;
    for (int j = tid; j < NN; j += 256)
        m = fmaxf(m, g_ed[(b * NN + j) * 4 + h]);
#pragma unroll
    for (int off = 16; off; off >>= 1)
        m = fmaxf(m, __shfl_xor_sync(0xffffffffu, m, off));
    if ((tid & 31) == 0) red[tid >> 5] = m;
    __syncthreads();
    if (tid == 0) {
        float mm = red[0];
#pragma unroll
        for (int i = 1; i < 8; i++) mm = fmaxf(mm, red[i]);
        g_gmax[w] = mm;
    }
}

// ================= GAT softmax + aggregate via mma.m16n8k16 =================
#define NTJ 24
__global__ void __launch_bounds__(256, 2) gat_agg2_kernel(
    const int* __restrict__ adj, float* __restrict__ out)
{
    extern __shared__ char smc[];
    __half* hp_s = (__half*)smc;                    // [64][72]
    __half* p_s  = (__half*)(smc + 9216);           // [8][16][72]
    float* ed_s  = (float*)(smc + 27648);           // [1536][4]
    unsigned* adjm = (unsigned*)(smc + 52224);      // [64]
    float* psum_s  = (float*)(smc + 52480);         // [8][16]

    const int tid = threadIdx.x;
    const int b = blockIdx.y;
    const int i0 = blockIdx.x * 32;
    const int warp = tid >> 5, lane = tid & 31;
    const int h_w = warp & 3, seg = warp >> 2;
    const int iw0 = i0 + seg * 16;
    const int i_loc = lane >> 1, jhalf = lane & 1;
    const int i_row = iw0 + i_loc;
    const int irc = (i_row < NN) ? i_row : NN - 1;

    for (int idx = tid; idx < 1536; idx += 256) {
        float4 v = make_float4(0.f, 0.f, 0.f, 0.f);
        if (idx < NN) v = reinterpret_cast<const float4*>(g_ed)[b * NN + idx];
        reinterpret_cast<float4*>(ed_s)[idx] = v;
    }

    const float es = g_es[(b * NN + irc) * 4 + h_w];
    const float M  = lrelu(es + g_gmax[b * 4 + h_w]);

    __half* pw = p_s + warp * (16 * 72);
    const unsigned pw_b  = smem_u32(pw);
    const unsigned hps_b = smem_u32(hp_s);

    float acc[8];
#pragma unroll
    for (int i = 0; i < 8; i++) acc[i] = 0.0f;
    float psl = 0.0f;

    for (int jt = 0; jt < NTJ; jt++) {
        const int jb = jt * 64;
        __syncthreads();
        for (int k = tid; k < 512; k += 256) {
            int jl = k >> 3, co = (k & 7) * 8;
            int j = jb + jl;
            uint4 v = make_uint4(0u, 0u, 0u, 0u);
            if (j < NN) v = *reinterpret_cast<const uint4*>(&g_hph[(b * NN + j) * 64 + co]);
            *reinterpret_cast<uint4*>(&hp_s[jl * 72 + co]) = v;
        }
#pragma unroll
        for (int p = 0; p < 8; p++) {
            int word = warp * 8 + p;
            int ii = i0 + (word >> 1);
            int jj = jb + (word & 1) * 32 + lane;
            int a = (ii < NN && jj < NN) ? adj[ii * NN + jj] : 0;
            unsigned m = __ballot_sync(0xffffffffu, a > 0);
            if (lane == 0) adjm[word] = m;
        }
        __syncthreads();

        {
            unsigned mword = adjm[(seg * 16 + i_loc) * 2 + jhalf];
            const float* edp = ed_s + (jb + jhalf * 32) * 4 + h_w;
            __half2* pst = reinterpret_cast<__half2*>(pw + i_loc * 72 + jhalf * 32);
#pragma unroll
            for (int q = 0; q < 32; q += 2) {
                float m0 = (float)((mword >> q) & 1u);
                float m1 = (float)((mword >> (q + 1)) & 1u);
                float p0 = m0 * __expf(lrelu(es + edp[q * 4]) - M);
                float p1 = m1 * __expf(lrelu(es + edp[(q + 1) * 4]) - M);
                psl += p0 + p1;
                pst[q >> 1] = __floats2half2_rn(p0, p1);
            }
        }
        __syncwarp();

        const unsigned a_addr0 = pw_b + (lane & 15) * 144 + ((lane >> 4) * 8) * 2;
        const unsigned b_addr0 = hps_b + ((lane & 15) * 72 + h_w * 16 + (lane >> 4) * 8) * 2;
#pragma unroll
        for (int kt = 0; kt < 4; kt++) {
            unsigned a0, a1, a2, a3, b0, b1, b2, b3;
            ldsm_x4 (a0, a1, a2, a3, a_addr0 + kt * 32);
            ldsm_x4t(b0, b1, b2, b3, b_addr0 + kt * 16 * 144);
            mma16816(acc[0], acc[1], acc[2], acc[3], a0, a1, a2, a3, b0, b1);
            mma16816(acc[4], acc[5], acc[6], acc[7], a0, a1, a2, a3, b2, b3);
        }
    }

    psl += __shfl_xor_sync(0xffffffffu, psl, 1);
    if (jhalf == 0) psum_s[warp * 16 + i_loc] = psl;
    __syncwarp();

    const int r_lo = iw0 + (lane >> 2), r_hi = r_lo + 8;
    const float inv_lo = 1.0f / psum_s[warp * 16 + (lane >> 2)];
    const float inv_hi = 1.0f / psum_s[warp * 16 + (lane >> 2) + 8];
    const int cb = h_w * 16 + (lane & 3) * 2;
    if (r_lo < NN) {
        *reinterpret_cast<float2*>(&out[(b * NN + r_lo) * 64 + cb]) =
            make_float2(fmaxf(acc[0] * inv_lo, 0.f), fmaxf(acc[1] * inv_lo, 0.f));
        *reinterpret_cast<float2*>(&out[(b * NN + r_lo) * 64 + cb + 8]) =
            make_float2(fmaxf(acc[4] * inv_lo, 0.f), fmaxf(acc[5] * inv_lo, 0.f));
    }
    if (r_hi < NN) {
        *reinterpret_cast<float2*>(&out[(b * NN + r_hi) * 64 + cb]) =
            make_float2(fmaxf(acc[2] * inv_hi, 0.f), fmaxf(acc[3] * inv_hi, 0.f));
        *reinterpret_cast<float2*>(&out[(b * NN + r_hi) * 64 + cb + 8]) =
            make_float2(fmaxf(acc[6] * inv_hi, 0.f), fmaxf(acc[7] * inv_hi, 0.f));
    }
}

// ================= output head =================
__global__ void __launch_bounds__(256) head_kernel(
    const float* __restrict__ oW, const float* __restrict__ ob,
    float* __restrict__ out)
{
    int s = blockIdx.x * 256 + threadIdx.x;
    if (s >= BNS) return;
    int b = s / NN, n = s % NN;
    float a0 = ob[0], a1 = ob[1], a2 = ob[2];
#pragma unroll 8
    for (int c = 0; c < 64; c++) {
        float v = g_h2[s * 64 + c];
        a0 += oW[c] * v; a1 += oW[64 + c] * v; a2 += oW[128 + c] * v;
    }
    out[(b * OUTD + 0) * NN + n] = a0;
    out[(b * OUTD + 1) * NN + n] = a1;
    out[(b * OUTD + 2) * NN + n] = a2;
}

extern "C" void kernel_launch(void* const* d_in, const int* in_sizes, int n_in,
                              void* d_out, int out_size) {
    const float* x    = (const float*)d_in[0];
    const int*   adj  = (const int*)  d_in[1];
    const float* Wih0 = (const float*)d_in[2];
    const float* Whh0 = (const float*)d_in[3];
    const float* bih0 = (const float*)d_in[4];
    const float* bhh0 = (const float*)d_in[5];
    const float* Wih1 = (const float*)d_in[6];
    const float* Whh1 = (const float*)d_in[7];
    const float* bih1 = (const float*)d_in[8];
    const float* bhh1 = (const float*)d_in[9];
    const float* g0W  = (const float*)d_in[10];
    const float* g0as = (const float*)d_in[11];
    const float* g0ad = (const float*)d_in[12];
    const float* g1W  = (const float*)d_in[13];
    const float* g1as = (const float*)d_in[14];
    const float* g1ad = (const float*)d_in[15];
    const float* outW = (const float*)d_in[16];
    const float* outb = (const float*)d_in[17];
    float* out = (float*)d_out;

    cudaFuncSetAttribute(lstm_fused_kernel<0>, cudaFuncAttributeMaxDynamicSharedMemorySize, 175616);
    cudaFuncSetAttribute(lstm_fused_kernel<1>, cudaFuncAttributeMaxDynamicSharedMemorySize, 175616);
    cudaFuncSetAttribute(gat_agg2_kernel,      cudaFuncAttributeMaxDynamicSharedMemorySize, 52992);

    float* g_h_p;  cudaGetSymbolAddress((void**)&g_h_p,  g_h);
    float* g_ho_p; cudaGetSymbolAddress((void**)&g_ho_p, g_ho);
    float* g_h2_p; cudaGetSymbolAddress((void**)&g_h2_p, g_h2);

    // launches 1-3: lstm0 + two dummies, so the fused lstm1 is launch #4
    // (the ncu capture in this harness consistently profiles launch #4).
    lstm_fused_kernel<0><<<150, 640, 175616>>>(x, Wih0, Whh0, bih0, bhh0);
    dummy_kernel<<<1, 64>>>();
    dummy_kernel<<<1, 64>>>();
    lstm_fused_kernel<1><<<150, 640, 175616>>>(x, Wih1, Whh1, bih1, bhh1);

    gat_prep_kernel<<<3000, 256>>>(g_h_p, g0W, g0as, g0ad);
    gmax_kernel<<<32, 256>>>();
    gat_agg2_kernel<<<dim3(47, 8), 256, 52992>>>(adj, g_ho_p);

    gat_prep_kernel<<<3000, 256>>>(g_ho_p, g1W, g1as, g1ad);
    gmax_kernel<<<32, 256>>>();
    gat_agg2_kernel<<<dim3(47, 8), 256, 52992>>>(adj, g_h2_p);

    head_kernel<<<47, 256>>>(outW, outb, out);
}